// round 13
// baseline (speedup 1.0000x reference)
#include <cuda_runtime.h>
#include <math.h>
#include <float.h>

#define N 384
#define NPIX (N*N)

// Only surviving intermediate: M/IRIL packed per scale (consumed by combine).
__device__ float2 g_MI[3][NPIX];        // .x = M, .y = IRIL

__device__ __forceinline__ int refl(int i) {
    if (i < 0) i = -i;
    if (i >= N) i = 2 * N - 2 - i;
    return i;
}

// Compare-exchange, descending (max first).
__device__ __forceinline__ void ced(float& x, float& y) {
    float hi = fmaxf(x, y), lo = fminf(x, y);
    x = hi; y = lo;
}

// Batcher sort-8, descending.
__device__ __forceinline__ void sort8_desc(float* v) {
    ced(v[0],v[1]); ced(v[2],v[3]); ced(v[4],v[5]); ced(v[6],v[7]);
    ced(v[0],v[2]); ced(v[1],v[3]); ced(v[4],v[6]); ced(v[5],v[7]);
    ced(v[1],v[2]); ced(v[5],v[6]);
    ced(v[0],v[4]); ced(v[1],v[5]); ced(v[2],v[6]); ced(v[3],v[7]);
    ced(v[2],v[4]); ced(v[3],v[5]);
    ced(v[1],v[2]); ced(v[3],v[4]); ced(v[5],v[6]);
}

__device__ __forceinline__ void sort9_desc(float* v) {
    sort8_desc(v);
    ced(v[7],v[8]); ced(v[6],v[7]); ced(v[5],v[6]); ced(v[4],v[5]);
    ced(v[3],v[4]); ced(v[2],v[3]); ced(v[1],v[2]); ced(v[0],v[1]);
}

__device__ __forceinline__ void top9_insert_desc(float* d, float v) {
    d[8] = fmaxf(d[8], v);
    ced(d[7],d[8]); ced(d[6],d[7]); ced(d[5],d[6]); ced(d[4],d[5]);
    ced(d[3],d[4]); ced(d[2],d[3]); ced(d[1],d[2]); ced(d[0],d[1]);
}

// Sorted-desc 9-list merge (validated R9): m[i]=max(A[i],B[8-i]) is the top-9
// multiset and is V-shaped (bitonic); 13-CE network sorts it.
__device__ __forceinline__ void merge9_sorted(const float* A, const float* B, float* O) {
    float v0 = fmaxf(A[0], B[8]);
    float v1 = fmaxf(A[1], B[7]);
    float v2 = fmaxf(A[2], B[6]);
    float v3 = fmaxf(A[3], B[5]);
    float v4 = fmaxf(A[4], B[4]);
    float v5 = fmaxf(A[5], B[3]);
    float v6 = fmaxf(A[6], B[2]);
    float v7 = fmaxf(A[7], B[1]);
    float v8 = fmaxf(A[8], B[0]);
    ced(v0, v8);
    ced(v1, v5); ced(v2, v6); ced(v3, v7); ced(v4, v8);
    ced(v1, v3); ced(v2, v4); ced(v5, v7); ced(v6, v8);
    ced(v1, v2); ced(v3, v4); ced(v5, v6); ced(v7, v8);
    O[0] = v0; O[1] = v1; O[2] = v2; O[3] = v3; O[4] = v4;
    O[5] = v5; O[6] = v6; O[7] = v7; O[8] = v8;
}

__device__ __forceinline__ float merge9_sum(const float* A, const float* B) {
    float s = fmaxf(A[0], B[8]);
    s += fmaxf(A[1], B[7]);
    s += fmaxf(A[2], B[6]);
    s += fmaxf(A[3], B[5]);
    s += fmaxf(A[4], B[4]);
    s += fmaxf(A[5], B[3]);
    s += fmaxf(A[6], B[2]);
    s += fmaxf(A[7], B[1]);
    s += fmaxf(A[8], B[0]);
    return s;
}

// ---------------------------------------------------------------------------
// K1 (fused): front-batched vertical load + group sorts + horizontal
// sparse-table merge. Block = 128 outputs of one row; 160 threads.
// Values UNSCALED (255 folded into M/avg).
// ---------------------------------------------------------------------------
#define RW 128
#define HALO 16
#define RC (RW + 2*HALO)   // 160

struct RowSmem {
    float L0[3][RC][9];
    float S0[3][RC];
    float sL[4][RC][9];
    float sS[4][RC];
};                          // 44.7 KB

template <int S, int SC, int TOPL>
__device__ __forceinline__ void process_scale(RowSmem& sm, int row, int colbase, int tid) {
#pragma unroll
    for (int k = 1; k <= TOPL; k++) {
        const int d = 1 << (k - 1);
        const int lim = RC - (1 << k) + 1;
        if (tid < lim) {
            const float* a  = (k == 1) ? sm.L0[SC][tid]     : sm.sL[k - 2][tid];
            const float* b  = (k == 1) ? sm.L0[SC][tid + d] : sm.sL[k - 2][tid + d];
            merge9_sorted(a, b, sm.sL[k - 1][tid]);
            float sa = (k == 1) ? sm.S0[SC][tid]     : sm.sS[k - 2][tid];
            float sb = (k == 1) ? sm.S0[SC][tid + d] : sm.sS[k - 2][tid + d];
            sm.sS[k - 1][tid] = sa + sb;
        }
        __syncthreads();
    }

    if (tid < RW) {
        float sum9, wsum;
        if (S == 33) {
            int a = tid;
            float E[9];
            merge9_sorted(sm.sL[3][a], sm.sL[3][a + 16], E);
            sum9 = merge9_sum(E, sm.L0[SC][a + 32]);
            wsum = sm.sS[3][a] + sm.sS[3][a + 16] + sm.S0[SC][a + 32];
        } else if (S == 23) {
            int a = tid + 5;
            float E[9], F[9];
            merge9_sorted(sm.sL[3][a],      sm.sL[1][a + 16], E);
            merge9_sorted(sm.sL[0][a + 20], sm.L0[SC][a + 22], F);
            sum9 = merge9_sum(E, F);
            wsum = sm.sS[3][a] + sm.sS[1][a + 16] + sm.sS[0][a + 20] + sm.S0[SC][a + 22];
        } else {
            int a = tid + 14;
            sum9 = merge9_sum(sm.sL[1][a], sm.L0[SC][a + 4]);
            wsum = sm.sS[1][a] + sm.S0[SC][a + 4];
        }
        float M = sum9 * (255.0f / 9.0f);
        float avg = wsum * (255.0f / (float)(S * S));
        g_MI[SC][row * N + colbase + tid] = make_float2(M, M - avg);
    }
    __syncthreads();
}

__global__ __launch_bounds__(RC) void rowfused(const float* __restrict__ x) {
    __shared__ RowSmem sm;
    const int row = blockIdx.y;
    const int colbase = blockIdx.x * RW;
    const int tid = threadIdx.x;
    const int gc = refl(colbase - HALO + tid);

    // Front-batched strip load: 33 independent loads, one latency exposure.
    float r[33];
#pragma unroll
    for (int i = 0; i < 33; i++)
        r[i] = __ldg(&x[refl(row - 16 + i) * N + gc]);

    // --- G1: r[14..18] -> S=5 snapshot ---
    float g1[9];
#pragma unroll
    for (int i = 0; i < 5; i++) g1[i] = r[14 + i];
    float sum5 = ((g1[0] + g1[1]) + (g1[2] + g1[3])) + g1[4];
    ced(g1[0],g1[1]); ced(g1[2],g1[3]); ced(g1[0],g1[2]); ced(g1[1],g1[3]); ced(g1[1],g1[2]);
    ced(g1[3],g1[4]); ced(g1[2],g1[3]); ced(g1[1],g1[2]); ced(g1[0],g1[1]);
#pragma unroll
    for (int i = 5; i < 9; i++) g1[i] = -FLT_MAX;
#pragma unroll
    for (int p = 0; p < 9; p++) sm.L0[0][tid][p] = g1[p];
    sm.S0[0][tid] = sum5;

    // --- G2: r[5..13], r[19..27] -> S=23 snapshot ---
    float A[9], B[9];
#pragma unroll
    for (int i = 0; i < 9; i++) { A[i] = r[5 + i]; B[i] = r[19 + i]; }
    float sumA = 0.0f, sumB = 0.0f;
#pragma unroll
    for (int i = 0; i < 9; i++) { sumA += A[i]; sumB += B[i]; }
    sort9_desc(A);
    sort9_desc(B);
    float g2[9], s23[9];
    merge9_sorted(A, B, g2);
    merge9_sorted(g1, g2, s23);
    float sum23 = sum5 + sumA + sumB;
#pragma unroll
    for (int p = 0; p < 9; p++) sm.L0[1][tid][p] = s23[p];
    sm.S0[1][tid] = sum23;

    // --- G3: r[0..4], r[28..31], cv=r[32] -> S=33 snapshot ---
    float C[9];
#pragma unroll
    for (int i = 0; i < 5; i++) C[i] = r[i];
#pragma unroll
    for (int i = 0; i < 4; i++) C[5 + i] = r[28 + i];
    float cv = r[32];
    float sumC = (((C[0] + C[1]) + (C[2] + C[3])) + ((C[4] + C[5]) + (C[6] + C[7]))) + C[8] + cv;
    sort9_desc(C);
    top9_insert_desc(C, cv);
    float s33[9];
    merge9_sorted(s23, C, s33);
#pragma unroll
    for (int p = 0; p < 9; p++) sm.L0[2][tid][p] = s33[p];
    sm.S0[2][tid] = sum23 + sumC;

    __syncthreads();

    process_scale<33, 2, 4>(sm, row, colbase, tid);
    process_scale<23, 1, 4>(sm, row, colbase, tid);
    process_scale<5, 0, 2>(sm, row, colbase, tid);
}

// ---------------------------------------------------------------------------
// K2: combine with ALL loads front-batched into registers (MLP ~36), then
// compute. No artificial register cap.
// ---------------------------------------------------------------------------
template <int D, int SC>
__device__ __forceinline__ void load_taps(int iy, int ix, float2 (&v)[9]) {
    int y0 = refl(iy - D), y1 = iy, y2 = refl(iy + D);
    int x0 = refl(ix - D), x1 = ix, x2 = refl(ix + D);
    v[0] = __ldg(&g_MI[SC][y0 * N + x0]);
    v[1] = __ldg(&g_MI[SC][y0 * N + x1]);
    v[2] = __ldg(&g_MI[SC][y0 * N + x2]);
    v[3] = __ldg(&g_MI[SC][y1 * N + x0]);
    v[4] = __ldg(&g_MI[SC][y1 * N + x1]);
    v[5] = __ldg(&g_MI[SC][y1 * N + x2]);
    v[6] = __ldg(&g_MI[SC][y2 * N + x0]);
    v[7] = __ldg(&g_MI[SC][y2 * N + x1]);
    v[8] = __ldg(&g_MI[SC][y2 * N + x2]);
}

__device__ __forceinline__ float combine_eval(const float2 (&v)[9], float gg) {
    float BE = fmaxf(fmaxf(fmaxf(v[0].x, v[1].x), fmaxf(v[2].x, v[3].x)),
                     fmaxf(fmaxf(v[5].x, v[6].x), fmaxf(v[7].x, v[8].x)));
    float SLCM = fmaxf((BE / gg - 1.0f) * gg, 0.0f);

    float WT = v[4].y;
    float mx = -FLT_MAX, s = 0.0f;
#pragma unroll
    for (int k = 0; k < 9; k++) {
        if (k == 4) continue;
        mx = fmaxf(mx, v[k].y);
        s += v[k].y;
    }
    float mean = s * 0.125f;
    float ss = 0.0f;
#pragma unroll
    for (int k = 0; k < 9; k++) {
        if (k == 4) continue;
        float d = v[k].y - mean;
        ss += d * d;
    }
    float WB = fmaxf(sqrtf(ss * (1.0f / 7.0f)), 5.0f);
    float WD = fmaxf(WT - mx, 0.0f);
    return SLCM * WT * WD / WB;
}

__global__ __launch_bounds__(256) void combine_all(const float* __restrict__ x,
                                                   float* __restrict__ out) {
    int idx = blockIdx.x * blockDim.x + threadIdx.x;
    if (idx >= NPIX) return;
    int iy = idx / N, ix = idx % N;

    // Front-batch: gaussian taps + all 27 float2 taps, then compute.
    float xs[9];
    {
        int y0 = refl(iy - 1), y2 = refl(iy + 1);
        int x0 = refl(ix - 1), x2 = refl(ix + 1);
        xs[0] = __ldg(&x[y0 * N + x0]); xs[1] = __ldg(&x[y0 * N + ix]); xs[2] = __ldg(&x[y0 * N + x2]);
        xs[3] = __ldg(&x[iy * N + x0]); xs[4] = __ldg(&x[iy * N + ix]); xs[5] = __ldg(&x[iy * N + x2]);
        xs[6] = __ldg(&x[y2 * N + x0]); xs[7] = __ldg(&x[y2 * N + ix]); xs[8] = __ldg(&x[y2 * N + x2]);
    }
    float2 v5[9], v23[9], v33[9];
    load_taps<5, 0>(iy, ix, v5);
    load_taps<23, 1>(iy, ix, v23);
    load_taps<33, 2>(iy, ix, v33);

    float acc = (xs[0] + xs[2] + xs[6] + xs[8])
              + 2.0f * (xs[1] + xs[3] + xs[5] + xs[7])
              + 4.0f * xs[4];
    float gg = acc * (255.0f / 16.0f) + 1.0f;

    float r = 0.0f;                                 // scale-3 branch is exactly 0
    r = fmaxf(r, combine_eval(v5, gg));
    r = fmaxf(r, combine_eval(v23, gg));
    r = fmaxf(r, combine_eval(v33, gg));
    out[idx] = r;
}

// ---------------------------------------------------------------------------
extern "C" void kernel_launch(void* const* d_in, const int* in_sizes, int n_in,
                              void* d_out, int out_size) {
    const float* x = (const float*)d_in[0];
    float* out = (float*)d_out;

    dim3 rgrid(N / RW, N);
    rowfused<<<rgrid, RC>>>(x);

    combine_all<<<(NPIX + 255) / 256, 256>>>(x, out);
}

// round 14
// speedup vs baseline: 1.0114x; 1.0114x over previous
#include <cuda_runtime.h>
#include <math.h>
#include <float.h>

#define N 384
#define NPIX (N*N)

__device__ float2 g_MI[3][NPIX];        // .x = M, .y = IRIL
__device__ float  g_g[NPIX];            // gaussian(255x)/16 + 1

__device__ __forceinline__ int refl(int i) {
    if (i < 0) i = -i;
    if (i >= N) i = 2 * N - 2 - i;
    return i;
}

__device__ __forceinline__ void ced(float& x, float& y) {
    float hi = fmaxf(x, y), lo = fminf(x, y);
    x = hi; y = lo;
}

__device__ __forceinline__ void sort8_desc(float* v) {
    ced(v[0],v[1]); ced(v[2],v[3]); ced(v[4],v[5]); ced(v[6],v[7]);
    ced(v[0],v[2]); ced(v[1],v[3]); ced(v[4],v[6]); ced(v[5],v[7]);
    ced(v[1],v[2]); ced(v[5],v[6]);
    ced(v[0],v[4]); ced(v[1],v[5]); ced(v[2],v[6]); ced(v[3],v[7]);
    ced(v[2],v[4]); ced(v[3],v[5]);
    ced(v[1],v[2]); ced(v[3],v[4]); ced(v[5],v[6]);
}

__device__ __forceinline__ void sort9_desc(float* v) {
    sort8_desc(v);
    ced(v[7],v[8]); ced(v[6],v[7]); ced(v[5],v[6]); ced(v[4],v[5]);
    ced(v[3],v[4]); ced(v[2],v[3]); ced(v[1],v[2]); ced(v[0],v[1]);
}

__device__ __forceinline__ void top9_insert_desc(float* d, float v) {
    d[8] = fmaxf(d[8], v);
    ced(d[7],d[8]); ced(d[6],d[7]); ced(d[5],d[6]); ced(d[4],d[5]);
    ced(d[3],d[4]); ced(d[2],d[3]); ced(d[1],d[2]); ced(d[0],d[1]);
}

// Sorted-desc 9-list merge (validated R9). Reads complete before writes: safe
// when O aliases A.
__device__ __forceinline__ void merge9_sorted(const float* A, const float* B, float* O) {
    float v0 = fmaxf(A[0], B[8]);
    float v1 = fmaxf(A[1], B[7]);
    float v2 = fmaxf(A[2], B[6]);
    float v3 = fmaxf(A[3], B[5]);
    float v4 = fmaxf(A[4], B[4]);
    float v5 = fmaxf(A[5], B[3]);
    float v6 = fmaxf(A[6], B[2]);
    float v7 = fmaxf(A[7], B[1]);
    float v8 = fmaxf(A[8], B[0]);
    ced(v0, v8);
    ced(v1, v5); ced(v2, v6); ced(v3, v7); ced(v4, v8);
    ced(v1, v3); ced(v2, v4); ced(v5, v7); ced(v6, v8);
    ced(v1, v2); ced(v3, v4); ced(v5, v6); ced(v7, v8);
    O[0] = v0; O[1] = v1; O[2] = v2; O[3] = v3; O[4] = v4;
    O[5] = v5; O[6] = v6; O[7] = v7; O[8] = v8;
}

__device__ __forceinline__ float merge9_sum(const float* A, const float* B) {
    float s = fmaxf(A[0], B[8]);
    s += fmaxf(A[1], B[7]);
    s += fmaxf(A[2], B[6]);
    s += fmaxf(A[3], B[5]);
    s += fmaxf(A[4], B[4]);
    s += fmaxf(A[5], B[3]);
    s += fmaxf(A[6], B[2]);
    s += fmaxf(A[7], B[1]);
    s += fmaxf(A[8], B[0]);
    return s;
}

// ---------------------------------------------------------------------------
#define RW 128
#define HALO 16
#define RC (RW + 2*HALO)   // 160

struct RowSmem {
    float L0[3][RC][9];
    float S0[3][RC];
    float sL[4][RC][9];
    float sS[4][RC];
    float gv[RC];          // vertical 1-2-1 gaussian partial
};

// Level builds with register-resident own operand: store own, read neighbor.
template <int S, int SC, int TOPL>
__device__ __forceinline__ void process_scale(RowSmem& sm, int row, int colbase, int tid) {
    float cur[9];
    float curS;
#pragma unroll
    for (int i = 0; i < 9; i++) cur[i] = sm.L0[SC][tid][i];
    curS = sm.S0[SC][tid];

#pragma unroll
    for (int k = 1; k <= TOPL; k++) {
        const int d = 1 << (k - 1);
        const int lim_prev = RC - (1 << (k - 1)) + 1;
        const int lim = RC - (1 << k) + 1;
        if (k >= 2 && tid < lim_prev) {      // publish own L_{k-1} (L0 already in smem)
#pragma unroll
            for (int i = 0; i < 9; i++) sm.sL[k - 2][tid][i] = cur[i];
            sm.sS[k - 2][tid] = curS;
        }
        __syncthreads();
        if (tid < lim) {
            const float* nb = (k == 1) ? sm.L0[SC][tid + d] : sm.sL[k - 2][tid + d];
            float nbS       = (k == 1) ? sm.S0[SC][tid + d] : sm.sS[k - 2][tid + d];
            merge9_sorted(cur, nb, cur);
            curS += nbS;
        }
    }
    // publish final level (needed at +offsets by queries)
    {
        const int limT = RC - (1 << TOPL) + 1;
        if (tid < limT) {
#pragma unroll
            for (int i = 0; i < 9; i++) sm.sL[TOPL - 1][tid][i] = cur[i];
            sm.sS[TOPL - 1][tid] = curS;
        }
    }
    __syncthreads();

    if (tid < RW) {
        float sum9, wsum;
        if (S == 33) {
            // a = tid: own regs hold L4[tid]
            float E[9];
            merge9_sorted(cur, sm.sL[3][tid + 16], E);
            sum9 = merge9_sum(E, sm.L0[SC][tid + 32]);
            wsum = curS + sm.sS[3][tid + 16] + sm.S0[SC][tid + 32];
        } else if (S == 23) {
            int a = tid + 5;
            float E[9], F[9];
            merge9_sorted(sm.sL[3][a],      sm.sL[1][a + 16], E);
            merge9_sorted(sm.sL[0][a + 20], sm.L0[SC][a + 22], F);
            sum9 = merge9_sum(E, F);
            wsum = sm.sS[3][a] + sm.sS[1][a + 16] + sm.sS[0][a + 20] + sm.S0[SC][a + 22];
        } else {
            int a = tid + 14;
            sum9 = merge9_sum(sm.sL[1][a], sm.L0[SC][a + 4]);
            wsum = sm.sS[1][a] + sm.S0[SC][a + 4];
        }
        float M = sum9 * (255.0f / 9.0f);
        float avg = wsum * (255.0f / (float)(S * S));
        g_MI[SC][row * N + colbase + tid] = make_float2(M, M - avg);
    }
    __syncthreads();
}

__global__ __launch_bounds__(RC) void rowfused(const float* __restrict__ x) {
    __shared__ RowSmem sm;
    const int row = blockIdx.y;
    const int colbase = blockIdx.x * RW;
    const int tid = threadIdx.x;
    const int gc = refl(colbase - HALO + tid);

    // Front-batched strip load.
    float r[33];
#pragma unroll
    for (int i = 0; i < 33; i++)
        r[i] = __ldg(&x[refl(row - 16 + i) * N + gc]);

    // Vertical gaussian partial (rows y-1,y,y+1 are r[15..17]).
    sm.gv[tid] = r[15] + 2.0f * r[16] + r[17];

    // --- G1: r[14..18] -> S=5 ---
    float g1[9];
#pragma unroll
    for (int i = 0; i < 5; i++) g1[i] = r[14 + i];
    float sum5 = ((g1[0] + g1[1]) + (g1[2] + g1[3])) + g1[4];
    ced(g1[0],g1[1]); ced(g1[2],g1[3]); ced(g1[0],g1[2]); ced(g1[1],g1[3]); ced(g1[1],g1[2]);
    ced(g1[3],g1[4]); ced(g1[2],g1[3]); ced(g1[1],g1[2]); ced(g1[0],g1[1]);
#pragma unroll
    for (int i = 5; i < 9; i++) g1[i] = -FLT_MAX;
#pragma unroll
    for (int p = 0; p < 9; p++) sm.L0[0][tid][p] = g1[p];
    sm.S0[0][tid] = sum5;

    // --- G2: r[5..13], r[19..27] -> S=23 ---
    float A[9], B[9];
#pragma unroll
    for (int i = 0; i < 9; i++) { A[i] = r[5 + i]; B[i] = r[19 + i]; }
    float sumA = 0.0f, sumB = 0.0f;
#pragma unroll
    for (int i = 0; i < 9; i++) { sumA += A[i]; sumB += B[i]; }
    sort9_desc(A);
    sort9_desc(B);
    float g2[9], s23[9];
    merge9_sorted(A, B, g2);
    merge9_sorted(g1, g2, s23);
    float sum23 = sum5 + sumA + sumB;
#pragma unroll
    for (int p = 0; p < 9; p++) sm.L0[1][tid][p] = s23[p];
    sm.S0[1][tid] = sum23;

    // --- G3: r[0..4], r[28..31], cv=r[32] -> S=33 ---
    float C[9];
#pragma unroll
    for (int i = 0; i < 5; i++) C[i] = r[i];
#pragma unroll
    for (int i = 0; i < 4; i++) C[5 + i] = r[28 + i];
    float cv = r[32];
    float sumC = (((C[0] + C[1]) + (C[2] + C[3])) + ((C[4] + C[5]) + (C[6] + C[7]))) + C[8] + cv;
    sort9_desc(C);
    top9_insert_desc(C, cv);
    float s33[9];
    merge9_sorted(s23, C, s33);
#pragma unroll
    for (int p = 0; p < 9; p++) sm.L0[2][tid][p] = s33[p];
    sm.S0[2][tid] = sum23 + sumC;

    __syncthreads();

    // Horizontal gaussian -> g plane.
    if (tid < RW) {
        int a = tid + HALO;
        float g = (sm.gv[a - 1] + 2.0f * sm.gv[a] + sm.gv[a + 1]) * (255.0f / 16.0f) + 1.0f;
        g_g[row * N + colbase + tid] = g;
    }

    process_scale<33, 2, 4>(sm, row, colbase, tid);
    process_scale<23, 1, 4>(sm, row, colbase, tid);
    process_scale<5, 0, 2>(sm, row, colbase, tid);
}

// ---------------------------------------------------------------------------
// K2: combine — g from plane; taps front-batched.
// ---------------------------------------------------------------------------
template <int D, int SC>
__device__ __forceinline__ void load_taps(int iy, int ix, float2 (&v)[9]) {
    int y0 = refl(iy - D), y1 = iy, y2 = refl(iy + D);
    int x0 = refl(ix - D), x1 = ix, x2 = refl(ix + D);
    v[0] = __ldg(&g_MI[SC][y0 * N + x0]);
    v[1] = __ldg(&g_MI[SC][y0 * N + x1]);
    v[2] = __ldg(&g_MI[SC][y0 * N + x2]);
    v[3] = __ldg(&g_MI[SC][y1 * N + x0]);
    v[4] = __ldg(&g_MI[SC][y1 * N + x1]);
    v[5] = __ldg(&g_MI[SC][y1 * N + x2]);
    v[6] = __ldg(&g_MI[SC][y2 * N + x0]);
    v[7] = __ldg(&g_MI[SC][y2 * N + x1]);
    v[8] = __ldg(&g_MI[SC][y2 * N + x2]);
}

__device__ __forceinline__ float combine_eval(const float2 (&v)[9], float gg) {
    float BE = fmaxf(fmaxf(fmaxf(v[0].x, v[1].x), fmaxf(v[2].x, v[3].x)),
                     fmaxf(fmaxf(v[5].x, v[6].x), fmaxf(v[7].x, v[8].x)));
    float SLCM = fmaxf((BE / gg - 1.0f) * gg, 0.0f);

    float WT = v[4].y;
    float mx = -FLT_MAX, s = 0.0f;
#pragma unroll
    for (int k = 0; k < 9; k++) {
        if (k == 4) continue;
        mx = fmaxf(mx, v[k].y);
        s += v[k].y;
    }
    float mean = s * 0.125f;
    float ss = 0.0f;
#pragma unroll
    for (int k = 0; k < 9; k++) {
        if (k == 4) continue;
        float d = v[k].y - mean;
        ss += d * d;
    }
    float WB = fmaxf(sqrtf(ss * (1.0f / 7.0f)), 5.0f);
    float WD = fmaxf(WT - mx, 0.0f);
    return SLCM * WT * WD / WB;
}

__global__ __launch_bounds__(256) void combine_all(float* __restrict__ out) {
    int idx = blockIdx.x * blockDim.x + threadIdx.x;
    if (idx >= NPIX) return;
    int iy = idx / N, ix = idx % N;

    float gg = __ldg(&g_g[idx]);
    float2 v5[9], v23[9], v33[9];
    load_taps<5, 0>(iy, ix, v5);
    load_taps<23, 1>(iy, ix, v23);
    load_taps<33, 2>(iy, ix, v33);

    float r = 0.0f;                                 // scale-3 branch is exactly 0
    r = fmaxf(r, combine_eval(v5, gg));
    r = fmaxf(r, combine_eval(v23, gg));
    r = fmaxf(r, combine_eval(v33, gg));
    out[idx] = r;
}

// ---------------------------------------------------------------------------
extern "C" void kernel_launch(void* const* d_in, const int* in_sizes, int n_in,
                              void* d_out, int out_size) {
    const float* x = (const float*)d_in[0];
    float* out = (float*)d_out;

    dim3 rgrid(N / RW, N);
    rowfused<<<rgrid, RC>>>(x);

    combine_all<<<(NPIX + 255) / 256, 256>>>(out);
}

// round 15
// speedup vs baseline: 1.0741x; 1.0620x over previous
#include <cuda_runtime.h>
#include <math.h>
#include <float.h>

#define N 384
#define NPIX (N*N)

__device__ float2 g_MI[3][NPIX];        // .x = M, .y = IRIL
__device__ float  g_g[NPIX];            // gaussian(255x)/16 + 1

__device__ __forceinline__ int refl(int i) {
    if (i < 0) i = -i;
    if (i >= N) i = 2 * N - 2 - i;
    return i;
}

__device__ __forceinline__ void ced(float& x, float& y) {
    float hi = fmaxf(x, y), lo = fminf(x, y);
    x = hi; y = lo;
}

__device__ __forceinline__ void sort8_desc(float* v) {
    ced(v[0],v[1]); ced(v[2],v[3]); ced(v[4],v[5]); ced(v[6],v[7]);
    ced(v[0],v[2]); ced(v[1],v[3]); ced(v[4],v[6]); ced(v[5],v[7]);
    ced(v[1],v[2]); ced(v[5],v[6]);
    ced(v[0],v[4]); ced(v[1],v[5]); ced(v[2],v[6]); ced(v[3],v[7]);
    ced(v[2],v[4]); ced(v[3],v[5]);
    ced(v[1],v[2]); ced(v[3],v[4]); ced(v[5],v[6]);
}

__device__ __forceinline__ void sort9_desc(float* v) {
    sort8_desc(v);
    ced(v[7],v[8]); ced(v[6],v[7]); ced(v[5],v[6]); ced(v[4],v[5]);
    ced(v[3],v[4]); ced(v[2],v[3]); ced(v[1],v[2]); ced(v[0],v[1]);
}

__device__ __forceinline__ void top9_insert_desc(float* d, float v) {
    d[8] = fmaxf(d[8], v);
    ced(d[7],d[8]); ced(d[6],d[7]); ced(d[5],d[6]); ced(d[4],d[5]);
    ced(d[3],d[4]); ced(d[2],d[3]); ced(d[1],d[2]); ced(d[0],d[1]);
}

// Sorted-desc 9-list merge (validated R9). Safe when O aliases A.
__device__ __forceinline__ void merge9_sorted(const float* A, const float* B, float* O) {
    float v0 = fmaxf(A[0], B[8]);
    float v1 = fmaxf(A[1], B[7]);
    float v2 = fmaxf(A[2], B[6]);
    float v3 = fmaxf(A[3], B[5]);
    float v4 = fmaxf(A[4], B[4]);
    float v5 = fmaxf(A[5], B[3]);
    float v6 = fmaxf(A[6], B[2]);
    float v7 = fmaxf(A[7], B[1]);
    float v8 = fmaxf(A[8], B[0]);
    ced(v0, v8);
    ced(v1, v5); ced(v2, v6); ced(v3, v7); ced(v4, v8);
    ced(v1, v3); ced(v2, v4); ced(v5, v7); ced(v6, v8);
    ced(v1, v2); ced(v3, v4); ced(v5, v6); ced(v7, v8);
    O[0] = v0; O[1] = v1; O[2] = v2; O[3] = v3; O[4] = v4;
    O[5] = v5; O[6] = v6; O[7] = v7; O[8] = v8;
}

__device__ __forceinline__ float merge9_sum(const float* A, const float* B) {
    float s = fmaxf(A[0], B[8]);
    s += fmaxf(A[1], B[7]);
    s += fmaxf(A[2], B[6]);
    s += fmaxf(A[3], B[5]);
    s += fmaxf(A[4], B[4]);
    s += fmaxf(A[5], B[3]);
    s += fmaxf(A[6], B[2]);
    s += fmaxf(A[7], B[1]);
    s += fmaxf(A[8], B[0]);
    return s;
}

// ---------------------------------------------------------------------------
#define RW 128
#define HALO 16
#define RC (RW + 2*HALO)   // 160

struct RowSmem {
    float L0[3][RC][9];
    float S0[3][RC];
    float sL[4][RC][9];
    float sS[4][RC];
    float gv[RC];
};

// Level builds with register-resident own operand (R14 structure).
template <int S, int SC, int TOPL>
__device__ __forceinline__ void process_scale(RowSmem& sm, int row, int colbase, int tid) {
    float cur[9];
    float curS;
#pragma unroll
    for (int i = 0; i < 9; i++) cur[i] = sm.L0[SC][tid][i];
    curS = sm.S0[SC][tid];

#pragma unroll
    for (int k = 1; k <= TOPL; k++) {
        const int d = 1 << (k - 1);
        const int lim_prev = RC - (1 << (k - 1)) + 1;
        const int lim = RC - (1 << k) + 1;
        if (k >= 2 && tid < lim_prev) {
#pragma unroll
            for (int i = 0; i < 9; i++) sm.sL[k - 2][tid][i] = cur[i];
            sm.sS[k - 2][tid] = curS;
        }
        __syncthreads();
        if (tid < lim) {
            const float* nb = (k == 1) ? sm.L0[SC][tid + d] : sm.sL[k - 2][tid + d];
            float nbS       = (k == 1) ? sm.S0[SC][tid + d] : sm.sS[k - 2][tid + d];
            merge9_sorted(cur, nb, cur);
            curS += nbS;
        }
    }
    {
        const int limT = RC - (1 << TOPL) + 1;
        if (tid < limT) {
#pragma unroll
            for (int i = 0; i < 9; i++) sm.sL[TOPL - 1][tid][i] = cur[i];
            sm.sS[TOPL - 1][tid] = curS;
        }
    }
    __syncthreads();

    if (tid < RW) {
        float sum9, wsum;
        if (S == 33) {
            float E[9];
            merge9_sorted(cur, sm.sL[3][tid + 16], E);
            sum9 = merge9_sum(E, sm.L0[SC][tid + 32]);
            wsum = curS + sm.sS[3][tid + 16] + sm.S0[SC][tid + 32];
        } else {   // S == 23
            int a = tid + 5;
            float E[9], F[9];
            merge9_sorted(sm.sL[3][a],      sm.sL[1][a + 16], E);
            merge9_sorted(sm.sL[0][a + 20], sm.L0[SC][a + 22], F);
            sum9 = merge9_sum(E, F);
            wsum = sm.sS[3][a] + sm.sS[1][a + 16] + sm.sS[0][a + 20] + sm.S0[SC][a + 22];
        }
        float M = sum9 * (255.0f / 9.0f);
        float avg = wsum * (255.0f / (float)(S * S));
        g_MI[SC][row * N + colbase + tid] = make_float2(M, M - avg);
    }
    __syncthreads();
}

__global__ __launch_bounds__(RC) void rowfused(const float* __restrict__ x) {
    __shared__ RowSmem sm;
    const int row = blockIdx.y;
    const int colbase = blockIdx.x * RW;
    const int tid = threadIdx.x;
    const int gc = refl(colbase - HALO + tid);

    float r[33];
#pragma unroll
    for (int i = 0; i < 33; i++)
        r[i] = __ldg(&x[refl(row - 16 + i) * N + gc]);

    sm.gv[tid] = r[15] + 2.0f * r[16] + r[17];

    // --- G1: r[14..18] -> S=5 L0 ---
    float g1[9];
#pragma unroll
    for (int i = 0; i < 5; i++) g1[i] = r[14 + i];
    float sum5 = ((g1[0] + g1[1]) + (g1[2] + g1[3])) + g1[4];
    ced(g1[0],g1[1]); ced(g1[2],g1[3]); ced(g1[0],g1[2]); ced(g1[1],g1[3]); ced(g1[1],g1[2]);
    ced(g1[3],g1[4]); ced(g1[2],g1[3]); ced(g1[1],g1[2]); ced(g1[0],g1[1]);
#pragma unroll
    for (int i = 5; i < 9; i++) g1[i] = -FLT_MAX;
#pragma unroll
    for (int p = 0; p < 9; p++) sm.L0[0][tid][p] = g1[p];
    sm.S0[0][tid] = sum5;

    // --- G2: r[5..13], r[19..27] -> S=23 L0 ---
    float A[9], B[9];
#pragma unroll
    for (int i = 0; i < 9; i++) { A[i] = r[5 + i]; B[i] = r[19 + i]; }
    float sumA = 0.0f, sumB = 0.0f;
#pragma unroll
    for (int i = 0; i < 9; i++) { sumA += A[i]; sumB += B[i]; }
    sort9_desc(A);
    sort9_desc(B);
    float g2[9], s23[9];
    merge9_sorted(A, B, g2);
    merge9_sorted(g1, g2, s23);
    float sum23 = sum5 + sumA + sumB;
#pragma unroll
    for (int p = 0; p < 9; p++) sm.L0[1][tid][p] = s23[p];
    sm.S0[1][tid] = sum23;

    // --- G3: r[0..4], r[28..31], cv=r[32] -> S=33 L0 ---
    float C[9];
#pragma unroll
    for (int i = 0; i < 5; i++) C[i] = r[i];
#pragma unroll
    for (int i = 0; i < 4; i++) C[5 + i] = r[28 + i];
    float cv = r[32];
    float sumC = (((C[0] + C[1]) + (C[2] + C[3])) + ((C[4] + C[5]) + (C[6] + C[7]))) + C[8] + cv;
    sort9_desc(C);
    top9_insert_desc(C, cv);
    float s33[9];
    merge9_sorted(s23, C, s33);
#pragma unroll
    for (int p = 0; p < 9; p++) sm.L0[2][tid][p] = s33[p];
    sm.S0[2][tid] = sum23 + sumC;

    __syncthreads();

    if (tid < RW) {
        int a = tid + HALO;
        float g = (sm.gv[a - 1] + 2.0f * sm.gv[a] + sm.gv[a + 1]) * (255.0f / 16.0f) + 1.0f;
        g_g[row * N + colbase + tid] = g;

        // S=5 DIRECT: merge 5 adjacent L0 lists in registers; no levels, no syncs.
        int b = tid + 14;
        float E[9], F[9], Gm[9];
        merge9_sorted(sm.L0[0][b],     sm.L0[0][b + 1], E);
        merge9_sorted(sm.L0[0][b + 2], sm.L0[0][b + 3], F);
        merge9_sorted(E, F, Gm);
        float sum9 = merge9_sum(Gm, sm.L0[0][b + 4]);
        float wsum = ((sm.S0[0][b] + sm.S0[0][b + 1]) + (sm.S0[0][b + 2] + sm.S0[0][b + 3]))
                   + sm.S0[0][b + 4];
        float M = sum9 * (255.0f / 9.0f);
        float avg = wsum * (255.0f / 25.0f);
        g_MI[0][row * N + colbase + tid] = make_float2(M, M - avg);
    }
    // No sync needed: process_scale<33> only touches L0[2]/S0[2]/sL/sS, and its
    // own first __syncthreads orders the sL writes.

    process_scale<33, 2, 4>(sm, row, colbase, tid);
    process_scale<23, 1, 4>(sm, row, colbase, tid);
}

// ---------------------------------------------------------------------------
// K2: combine — reduced math: SLCM = max(BE - g, 0); moments variance; rsqrt.
// ---------------------------------------------------------------------------
template <int D, int SC>
__device__ __forceinline__ void load_taps(int iy, int ix, float2 (&v)[9]) {
    int y0 = refl(iy - D), y1 = iy, y2 = refl(iy + D);
    int x0 = refl(ix - D), x1 = ix, x2 = refl(ix + D);
    v[0] = __ldg(&g_MI[SC][y0 * N + x0]);
    v[1] = __ldg(&g_MI[SC][y0 * N + x1]);
    v[2] = __ldg(&g_MI[SC][y0 * N + x2]);
    v[3] = __ldg(&g_MI[SC][y1 * N + x0]);
    v[4] = __ldg(&g_MI[SC][y1 * N + x1]);
    v[5] = __ldg(&g_MI[SC][y1 * N + x2]);
    v[6] = __ldg(&g_MI[SC][y2 * N + x0]);
    v[7] = __ldg(&g_MI[SC][y2 * N + x1]);
    v[8] = __ldg(&g_MI[SC][y2 * N + x2]);
}

__device__ __forceinline__ float combine_eval(const float2 (&v)[9], float gg) {
    float BE = fmaxf(fmaxf(fmaxf(v[0].x, v[1].x), fmaxf(v[2].x, v[3].x)),
                     fmaxf(fmaxf(v[5].x, v[6].x), fmaxf(v[7].x, v[8].x)));
    float SLCM = fmaxf(BE - gg, 0.0f);          // == max((BE/g-1)*g, 0)

    float WT = v[4].y;
    float mx = -FLT_MAX, sy = 0.0f, sy2 = 0.0f;
#pragma unroll
    for (int k = 0; k < 9; k++) {
        if (k == 4) continue;
        float y = v[k].y;
        mx = fmaxf(mx, y);
        sy += y;
        sy2 = fmaf(y, y, sy2);
    }
    float ss = fmaxf(sy2 - sy * sy * 0.125f, 0.0f);
    // 1/WB = min(1/std, 1/5); std below the clamp is irrelevant (masked by max).
    float invWB = fminf(rsqrtf(ss * (1.0f / 7.0f)), 0.2f);
    float WD = fmaxf(WT - mx, 0.0f);
    return SLCM * WT * WD * invWB;
}

__global__ __launch_bounds__(256) void combine_all(float* __restrict__ out) {
    int idx = blockIdx.x * blockDim.x + threadIdx.x;
    if (idx >= NPIX) return;
    int iy = idx / N, ix = idx % N;

    float gg = __ldg(&g_g[idx]);
    float2 v5[9], v23[9], v33[9];
    load_taps<5, 0>(iy, ix, v5);
    load_taps<23, 1>(iy, ix, v23);
    load_taps<33, 2>(iy, ix, v33);

    float r = 0.0f;                                 // scale-3 branch is exactly 0
    r = fmaxf(r, combine_eval(v5, gg));
    r = fmaxf(r, combine_eval(v23, gg));
    r = fmaxf(r, combine_eval(v33, gg));
    out[idx] = r;
}

// ---------------------------------------------------------------------------
extern "C" void kernel_launch(void* const* d_in, const int* in_sizes, int n_in,
                              void* d_out, int out_size) {
    const float* x = (const float*)d_in[0];
    float* out = (float*)d_out;

    dim3 rgrid(N / RW, N);
    rowfused<<<rgrid, RC>>>(x);

    combine_all<<<(NPIX + 255) / 256, 256>>>(out);
}

// round 16
// speedup vs baseline: 1.1094x; 1.0328x over previous
#include <cuda_runtime.h>
#include <math.h>
#include <float.h>

#define N 384
#define NPIX (N*N)

__device__ float2 g_MI[3][NPIX];        // .x = M, .y = IRIL
__device__ float  g_g[NPIX];            // gaussian(255x)/16 + 1

__device__ __forceinline__ int refl(int i) {
    if (i < 0) i = -i;
    if (i >= N) i = 2 * N - 2 - i;
    return i;
}

__device__ __forceinline__ void ced(float& x, float& y) {
    float hi = fmaxf(x, y), lo = fminf(x, y);
    x = hi; y = lo;
}

__device__ __forceinline__ void sort8_desc(float* v) {
    ced(v[0],v[1]); ced(v[2],v[3]); ced(v[4],v[5]); ced(v[6],v[7]);
    ced(v[0],v[2]); ced(v[1],v[3]); ced(v[4],v[6]); ced(v[5],v[7]);
    ced(v[1],v[2]); ced(v[5],v[6]);
    ced(v[0],v[4]); ced(v[1],v[5]); ced(v[2],v[6]); ced(v[3],v[7]);
    ced(v[2],v[4]); ced(v[3],v[5]);
    ced(v[1],v[2]); ced(v[3],v[4]); ced(v[5],v[6]);
}

__device__ __forceinline__ void sort9_desc(float* v) {
    sort8_desc(v);
    ced(v[7],v[8]); ced(v[6],v[7]); ced(v[5],v[6]); ced(v[4],v[5]);
    ced(v[3],v[4]); ced(v[2],v[3]); ced(v[1],v[2]); ced(v[0],v[1]);
}

__device__ __forceinline__ void top9_insert_desc(float* d, float v) {
    d[8] = fmaxf(d[8], v);
    ced(d[7],d[8]); ced(d[6],d[7]); ced(d[5],d[6]); ced(d[4],d[5]);
    ced(d[3],d[4]); ced(d[2],d[3]); ced(d[1],d[2]); ced(d[0],d[1]);
}

// Sorted-desc 9-list merge (validated R9). Safe when O aliases A.
__device__ __forceinline__ void merge9_sorted(const float* A, const float* B, float* O) {
    float v0 = fmaxf(A[0], B[8]);
    float v1 = fmaxf(A[1], B[7]);
    float v2 = fmaxf(A[2], B[6]);
    float v3 = fmaxf(A[3], B[5]);
    float v4 = fmaxf(A[4], B[4]);
    float v5 = fmaxf(A[5], B[3]);
    float v6 = fmaxf(A[6], B[2]);
    float v7 = fmaxf(A[7], B[1]);
    float v8 = fmaxf(A[8], B[0]);
    ced(v0, v8);
    ced(v1, v5); ced(v2, v6); ced(v3, v7); ced(v4, v8);
    ced(v1, v3); ced(v2, v4); ced(v5, v7); ced(v6, v8);
    ced(v1, v2); ced(v3, v4); ced(v5, v6); ced(v7, v8);
    O[0] = v0; O[1] = v1; O[2] = v2; O[3] = v3; O[4] = v4;
    O[5] = v5; O[6] = v6; O[7] = v7; O[8] = v8;
}

__device__ __forceinline__ float merge9_sum(const float* A, const float* B) {
    float s = fmaxf(A[0], B[8]);
    s += fmaxf(A[1], B[7]);
    s += fmaxf(A[2], B[6]);
    s += fmaxf(A[3], B[5]);
    s += fmaxf(A[4], B[4]);
    s += fmaxf(A[5], B[3]);
    s += fmaxf(A[6], B[2]);
    s += fmaxf(A[7], B[1]);
    s += fmaxf(A[8], B[0]);
    return s;
}

// float2-vectorized list load/store for padded (10-float) smem rows.
__device__ __forceinline__ void ld_list(const float* s, float* v) {
    float2 a = *reinterpret_cast<const float2*>(s);
    float2 b = *reinterpret_cast<const float2*>(s + 2);
    float2 c = *reinterpret_cast<const float2*>(s + 4);
    float2 d = *reinterpret_cast<const float2*>(s + 6);
    v[0]=a.x; v[1]=a.y; v[2]=b.x; v[3]=b.y; v[4]=c.x; v[5]=c.y; v[6]=d.x; v[7]=d.y;
    v[8] = s[8];
}
__device__ __forceinline__ void st_list(float* s, const float* v) {
    *reinterpret_cast<float2*>(s)     = make_float2(v[0], v[1]);
    *reinterpret_cast<float2*>(s + 2) = make_float2(v[2], v[3]);
    *reinterpret_cast<float2*>(s + 4) = make_float2(v[4], v[5]);
    *reinterpret_cast<float2*>(s + 6) = make_float2(v[6], v[7]);
    s[8] = v[8];
}

// ---------------------------------------------------------------------------
#define RW 128
#define HALO 16
#define RC (RW + 2*HALO)   // 160

struct RowSmem {
    float L0[3][RC][9];    // 17280 B (scalar access)
    float S0[3][RC];       // 1920
    float sL[4][RC][10];   // 25600  (padded -> float2 access, 8B-aligned)
    float sS[4][RC];       // 2560   (sS[0] doubles as gv during the early phase)
};                          // 47360 B static

// Level builds; k=1 has no preceding sync (L0 ordered by the initial sync),
// and there is no trailing sync (subsumed by the next scale's k=2 sync —
// first conflicting write sL[0] is barrier-separated from all prior readers).
template <int S, int SC, int TOPL>
__device__ __forceinline__ void process_scale(RowSmem& sm, int row, int colbase, int tid) {
    float cur[9];
    float curS;
#pragma unroll
    for (int i = 0; i < 9; i++) cur[i] = sm.L0[SC][tid][i];
    curS = sm.S0[SC][tid];

    // k = 1 (neighbor from L0, scalar; no sync needed)
    if (tid < RC - 1) {
        merge9_sorted(cur, sm.L0[SC][tid + 1], cur);
        curS += sm.S0[SC][tid + 1];
    }

#pragma unroll
    for (int k = 2; k <= TOPL; k++) {
        const int d = 1 << (k - 1);
        const int lim_prev = RC - (1 << (k - 1)) + 1;
        const int lim = RC - (1 << k) + 1;
        if (tid < lim_prev) {
            st_list(sm.sL[k - 2][tid], cur);
            sm.sS[k - 2][tid] = curS;
        }
        __syncthreads();
        if (tid < lim) {
            float nb[9];
            ld_list(sm.sL[k - 2][tid + d], nb);
            merge9_sorted(cur, nb, cur);
            curS += sm.sS[k - 2][tid + d];
        }
    }
    {
        const int limT = RC - (1 << TOPL) + 1;
        if (tid < limT) {
            st_list(sm.sL[TOPL - 1][tid], cur);
            sm.sS[TOPL - 1][tid] = curS;
        }
    }
    __syncthreads();

    if (tid < RW) {
        float sum9, wsum;
        if (S == 33) {
            float nb[9], E[9];
            ld_list(sm.sL[3][tid + 16], nb);
            merge9_sorted(cur, nb, E);
            sum9 = merge9_sum(E, sm.L0[SC][tid + 32]);
            wsum = curS + sm.sS[3][tid + 16] + sm.S0[SC][tid + 32];
        } else {   // S == 23
            int a = tid + 5;
            float p[9], q[9], r2[9], E[9], F[9];
            ld_list(sm.sL[3][a], p);
            ld_list(sm.sL[1][a + 16], q);
            ld_list(sm.sL[0][a + 20], r2);
            merge9_sorted(p, q, E);
            merge9_sorted(r2, sm.L0[SC][a + 22], F);
            sum9 = merge9_sum(E, F);
            wsum = sm.sS[3][a] + sm.sS[1][a + 16] + sm.sS[0][a + 20] + sm.S0[SC][a + 22];
        }
        float M = sum9 * (255.0f / 9.0f);
        float avg = wsum * (255.0f / (float)(S * S));
        g_MI[SC][row * N + colbase + tid] = make_float2(M, M - avg);
    }
    // no trailing sync
}

__global__ __launch_bounds__(RC) void rowfused(const float* __restrict__ x) {
    __shared__ RowSmem sm;
    float* gv = sm.sS[0];                 // alias: dead before sS[0] first written
    const int row = blockIdx.y;
    const int colbase = blockIdx.x * RW;
    const int tid = threadIdx.x;
    const int gc = refl(colbase - HALO + tid);

    // Strip load: fast path (no row reflection) for interior rows — the branch
    // is block-uniform and the 33 loads become immediate-offset LDGs.
    float r[33];
    if (row >= HALO && row < N - HALO) {
        const float* p = x + (row - HALO) * N + gc;
#pragma unroll
        for (int i = 0; i < 33; i++) r[i] = __ldg(&p[i * N]);
    } else {
#pragma unroll
        for (int i = 0; i < 33; i++)
            r[i] = __ldg(&x[refl(row - HALO + i) * N + gc]);
    }

    gv[tid] = r[15] + 2.0f * r[16] + r[17];

    // --- G1: r[14..18] -> S=5 L0 ---
    float g1[9];
#pragma unroll
    for (int i = 0; i < 5; i++) g1[i] = r[14 + i];
    float sum5 = ((g1[0] + g1[1]) + (g1[2] + g1[3])) + g1[4];
    ced(g1[0],g1[1]); ced(g1[2],g1[3]); ced(g1[0],g1[2]); ced(g1[1],g1[3]); ced(g1[1],g1[2]);
    ced(g1[3],g1[4]); ced(g1[2],g1[3]); ced(g1[1],g1[2]); ced(g1[0],g1[1]);
#pragma unroll
    for (int i = 5; i < 9; i++) g1[i] = -FLT_MAX;
#pragma unroll
    for (int p = 0; p < 9; p++) sm.L0[0][tid][p] = g1[p];
    sm.S0[0][tid] = sum5;

    // --- G2: r[5..13], r[19..27] -> S=23 L0 ---
    float A[9], B[9];
#pragma unroll
    for (int i = 0; i < 9; i++) { A[i] = r[5 + i]; B[i] = r[19 + i]; }
    float sumA = 0.0f, sumB = 0.0f;
#pragma unroll
    for (int i = 0; i < 9; i++) { sumA += A[i]; sumB += B[i]; }
    sort9_desc(A);
    sort9_desc(B);
    float g2[9], s23[9];
    merge9_sorted(A, B, g2);
    merge9_sorted(g1, g2, s23);
    float sum23 = sum5 + sumA + sumB;
#pragma unroll
    for (int p = 0; p < 9; p++) sm.L0[1][tid][p] = s23[p];
    sm.S0[1][tid] = sum23;

    // --- G3: r[0..4], r[28..31], cv=r[32] -> S=33 L0 ---
    float C[9];
#pragma unroll
    for (int i = 0; i < 5; i++) C[i] = r[i];
#pragma unroll
    for (int i = 0; i < 4; i++) C[5 + i] = r[28 + i];
    float cv = r[32];
    float sumC = (((C[0] + C[1]) + (C[2] + C[3])) + ((C[4] + C[5]) + (C[6] + C[7]))) + C[8] + cv;
    sort9_desc(C);
    top9_insert_desc(C, cv);
    float s33[9];
    merge9_sorted(s23, C, s33);
#pragma unroll
    for (int p = 0; p < 9; p++) sm.L0[2][tid][p] = s33[p];
    sm.S0[2][tid] = sum23 + sumC;

    __syncthreads();   // INITIAL: L0/S0/gv visible

    if (tid < RW) {
        int a = tid + HALO;
        float g = (gv[a - 1] + 2.0f * gv[a] + gv[a + 1]) * (255.0f / 16.0f) + 1.0f;
        g_g[row * N + colbase + tid] = g;

        // S=5 DIRECT: merge 5 adjacent L0 lists in registers.
        int b = tid + 14;
        float E[9], F[9], Gm[9];
        merge9_sorted(sm.L0[0][b],     sm.L0[0][b + 1], E);
        merge9_sorted(sm.L0[0][b + 2], sm.L0[0][b + 3], F);
        merge9_sorted(E, F, Gm);
        float sum9 = merge9_sum(Gm, sm.L0[0][b + 4]);
        float wsum = ((sm.S0[0][b] + sm.S0[0][b + 1]) + (sm.S0[0][b + 2] + sm.S0[0][b + 3]))
                   + sm.S0[0][b + 4];
        float M = sum9 * (255.0f / 9.0f);
        float avg = wsum * (255.0f / 25.0f);
        g_MI[0][row * N + colbase + tid] = make_float2(M, M - avg);
    }
    __syncthreads();   // BARRIER-A: gv (alias sS[0]) reads done before sS[0] writes

    process_scale<33, 2, 4>(sm, row, colbase, tid);
    process_scale<23, 1, 4>(sm, row, colbase, tid);
}

// ---------------------------------------------------------------------------
// K2: combine — interior fast path with compile-time tap offsets.
// ---------------------------------------------------------------------------
template <int D, int SC>
__device__ __forceinline__ void load_taps_fast(int idx, float2 (&v)[9]) {
    const float2* c = &g_MI[SC][idx];
    v[0] = __ldg(c - D * N - D);
    v[1] = __ldg(c - D * N);
    v[2] = __ldg(c - D * N + D);
    v[3] = __ldg(c - D);
    v[4] = __ldg(c);
    v[5] = __ldg(c + D);
    v[6] = __ldg(c + D * N - D);
    v[7] = __ldg(c + D * N);
    v[8] = __ldg(c + D * N + D);
}

template <int D, int SC>
__device__ __forceinline__ void load_taps(int iy, int ix, float2 (&v)[9]) {
    int y0 = refl(iy - D), y1 = iy, y2 = refl(iy + D);
    int x0 = refl(ix - D), x1 = ix, x2 = refl(ix + D);
    v[0] = __ldg(&g_MI[SC][y0 * N + x0]);
    v[1] = __ldg(&g_MI[SC][y0 * N + x1]);
    v[2] = __ldg(&g_MI[SC][y0 * N + x2]);
    v[3] = __ldg(&g_MI[SC][y1 * N + x0]);
    v[4] = __ldg(&g_MI[SC][y1 * N + x1]);
    v[5] = __ldg(&g_MI[SC][y1 * N + x2]);
    v[6] = __ldg(&g_MI[SC][y2 * N + x0]);
    v[7] = __ldg(&g_MI[SC][y2 * N + x1]);
    v[8] = __ldg(&g_MI[SC][y2 * N + x2]);
}

__device__ __forceinline__ float combine_eval(const float2 (&v)[9], float gg) {
    float BE = fmaxf(fmaxf(fmaxf(v[0].x, v[1].x), fmaxf(v[2].x, v[3].x)),
                     fmaxf(fmaxf(v[5].x, v[6].x), fmaxf(v[7].x, v[8].x)));
    float SLCM = fmaxf(BE - gg, 0.0f);

    float WT = v[4].y;
    float mx = -FLT_MAX, sy = 0.0f, sy2 = 0.0f;
#pragma unroll
    for (int k = 0; k < 9; k++) {
        if (k == 4) continue;
        float y = v[k].y;
        mx = fmaxf(mx, y);
        sy += y;
        sy2 = fmaf(y, y, sy2);
    }
    float ss = fmaxf(sy2 - sy * sy * 0.125f, 0.0f);
    float invWB = fminf(rsqrtf(ss * (1.0f / 7.0f)), 0.2f);
    float WD = fmaxf(WT - mx, 0.0f);
    return SLCM * WT * WD * invWB;
}

__global__ __launch_bounds__(256) void combine_all(float* __restrict__ out) {
    int idx = blockIdx.x * blockDim.x + threadIdx.x;
    if (idx >= NPIX) return;
    int iy = idx / N, ix = idx % N;

    float gg = __ldg(&g_g[idx]);
    float2 v5[9], v23[9], v33[9];
    if (iy >= 33 && iy < N - 33 && ix >= 33 && ix < N - 33) {
        load_taps_fast<5, 0>(idx, v5);
        load_taps_fast<23, 1>(idx, v23);
        load_taps_fast<33, 2>(idx, v33);
    } else {
        load_taps<5, 0>(iy, ix, v5);
        load_taps<23, 1>(iy, ix, v23);
        load_taps<33, 2>(iy, ix, v33);
    }

    float r = 0.0f;                                 // scale-3 branch is exactly 0
    r = fmaxf(r, combine_eval(v5, gg));
    r = fmaxf(r, combine_eval(v23, gg));
    r = fmaxf(r, combine_eval(v33, gg));
    out[idx] = r;
}

// ---------------------------------------------------------------------------
extern "C" void kernel_launch(void* const* d_in, const int* in_sizes, int n_in,
                              void* d_out, int out_size) {
    const float* x = (const float*)d_in[0];
    float* out = (float*)d_out;

    dim3 rgrid(N / RW, N);
    rowfused<<<rgrid, RC>>>(x);

    combine_all<<<(NPIX + 255) / 256, 256>>>(out);
}